// round 5
// baseline (speedup 1.0000x reference)
#include <cuda_runtime.h>
#include <cuda_bf16.h>
#include <cstdint>

#define NUM_EMB 1024
#define EMB_DIM 64
#define NPIX    65536      // 64 * 32 * 32 pixels
#define NELEM   4194304    // 64 * 64 * 32 * 32
#define NBLK    256        // finish-kernel blocks (256 px each)
#define CAP     32         // candidate buffer per pixel
#define DELTA   2.5e-3f    // screen window >= 2*max_int8_err + grid slop

#define SA      9.0f                       // 2x quant scale
#define SB      (127.0f * 1024.0f)         // e quant scale
#define INVS    (1.0f / (9.0f * 127.0f * 1024.0f))

// ---------------- device scratch (no allocs allowed) ----------------
__device__ float    g_codeS[NUM_EMB];
__device__ int      g_counts[NUM_EMB];
__device__ double   g_part[NBLK];
__device__ int      g_ticket;
__device__ uint4    g_bfrag[128 * 32];            // [tile][lane] int8 B fragments (64 KB)
__device__ int      g_cnt[NPIX];
__device__ unsigned short g_cidx[NPIX * CAP];
__device__ float    g_cd[NPIX * CAP];
__device__ float    g_best[NPIX];

// ---------------- helpers ----------------
static __device__ __forceinline__ unsigned pack4s8(int v0, int v1, int v2, int v3) {
    return (unsigned)(v0 & 255) | ((unsigned)(v1 & 255) << 8)
         | ((unsigned)(v2 & 255) << 16) | ((unsigned)(v3 & 255) << 24);
}
static __device__ __forceinline__ int q8x(float v) {      // quantize 2x (clamped)
    int r = __float2int_rn(v * SA);
    return max(-127, min(127, r));
}
static __device__ __forceinline__ void imma16832(int& c0, int& c1, int& c2, int& c3,
                                                 unsigned a0, unsigned a1, unsigned a2, unsigned a3,
                                                 unsigned b0, unsigned b1) {
    asm volatile("mma.sync.aligned.m16n8k32.row.col.s32.s8.s8.s32 "
                 "{%0,%1,%2,%3}, {%4,%5,%6,%7}, {%8,%9}, {%0,%1,%2,%3};"
                 : "+r"(c0), "+r"(c1), "+r"(c2), "+r"(c3)
                 : "r"(a0), "r"(a1), "r"(a2), "r"(a3), "r"(b0), "r"(b1));
}
static __device__ __forceinline__ void append_cand(int pix, int idx, float d) {
    int slot = atomicAdd(&g_cnt[pix], 1);
    if (slot < CAP) {
        g_cidx[pix * CAP + slot] = (unsigned short)idx;
        g_cd[pix * CAP + slot]   = d;
    }
}

// ---------------- kernel 1: code norms + int8 B fragments + resets ----------------
// grid 40 x 128: blocks 0..7 -> norms (1024 thr), blocks 8..39 -> fragments (4096 thr)
__global__ void __launch_bounds__(128) prep_kernel(const float* __restrict__ w) {
    int gid = blockIdx.x * 128 + threadIdx.x;

    if (blockIdx.x < 8) {                            // exact code norms (validated order)
        int k = gid;
        const float* row = w + k * EMB_DIM;
        float s = 0.0f;
        #pragma unroll
        for (int d = 0; d < EMB_DIM; d++)
            s = __fadd_rn(s, __fmul_rn(row[d], row[d]));
        g_codeS[k]  = s;
        g_counts[k] = 0;
        if (k == 0) g_ticket = 0;
        return;
    }

    // int8 B fragments for mma.m16n8k32.s8 (col-major B = codes)
    int f    = gid - 1024;                           // 0..4095
    int tile = f >> 5;
    int lane = f & 31;
    int n    = tile * 8 + (lane >> 2);               // code row
    int q    = lane & 3;
    const float* e = w + n * EMB_DIM;

    unsigned bw[4];
    #pragma unroll
    for (int g = 0; g < 4; g++) {                    // granules: k = g*16 + 4q + 0..3
        int k0 = g * 16 + 4 * q;
        bw[g] = pack4s8(__float2int_rn(e[k0]     * SB),
                        __float2int_rn(e[k0 + 1] * SB),
                        __float2int_rn(e[k0 + 2] * SB),
                        __float2int_rn(e[k0 + 3] * SB));
    }
    // x = instr0.b0 (k0-15), y = instr0.b1 (k16-31), z = instr1.b0 (k32-47), w = instr1.b1 (k48-63)
    g_bfrag[tile * 32 + lane] = make_uint4(bw[0], bw[1], bw[2], bw[3]);
}

// ---------------- kernel 2: IMMA int8 screen, full-codebook smem ----------------
__global__ void __launch_bounds__(256) argmin_kernel(const float* __restrict__ x) {
    extern __shared__ char smem[];
    uint4* sB  = (uint4*)smem;                       // 4096 uint4 (64 KB)
    float* sBN = (float*)(smem + 65536);             // 1024 f32 (4 KB)

    int tid  = threadIdx.x;
    int warp = tid >> 5;
    int lane = tid & 31;
    int q    = lane & 3;
    int r    = lane >> 2;

    #pragma unroll
    for (int i = 0; i < 16; i++) sB[tid + 256 * i] = g_bfrag[tid + 256 * i];
    #pragma unroll
    for (int i = 0; i < 4; i++) sBN[tid + 256 * i] = g_codeS[tid + 256 * i];

    int p0b = blockIdx.x * 128;
    if (tid < 128) g_cnt[p0b + tid] = 0;

    // ---- int8 A fragments for this warp's 16 pixels ----
    int p0 = p0b + warp * 16;
    const float* xb = x + (size_t)(p0 >> 10) * 65536 + (p0 & 1023);  // NCHW, dim stride 1024

    unsigned A0[4], A1[4];                           // [instr][areg]
    #pragma unroll
    for (int h = 0; h < 2; h++) {
        #pragma unroll
        for (int gsub = 0; gsub < 2; gsub++) {
            int kb = h * 32 + gsub * 16 + 4 * q;
            #pragma unroll
            for (int rh = 0; rh < 2; rh++) {
                int rr = r + 8 * rh;
                unsigned v = pack4s8(
                    q8x(2.0f * xb[(size_t)kb       * 1024 + rr]),
                    q8x(2.0f * xb[(size_t)(kb + 1) * 1024 + rr]),
                    q8x(2.0f * xb[(size_t)(kb + 2) * 1024 + rr]),
                    q8x(2.0f * xb[(size_t)(kb + 3) * 1024 + rr]));
                if (h == 0) A0[gsub * 2 + rh] = v;   // a0=(k,r) a1=(k,r+8) a2=(k+16,r) a3=(k+16,r+8)
                else        A1[gsub * 2 + rh] = v;
            }
        }
    }
    // reorder to PTX a0..a3: a0=(g0,r), a1=(g0,r+8)? NOTE: a1 is row r+8 same k; a2 k+16 row r.
    // Our fill: idx0=(g0,r), idx1=(g0,r+8), idx2=(g16,r), idx3=(g16,r+8) == a0,a1,a2,a3. correct.

    __syncthreads();

    float bestL = 3.4e38f, bestH = 3.4e38f;

    for (int gt = 0; gt < 32; gt++) {                // 4 tiles per group
        float dL[8], dH[8];
        #pragma unroll
        for (int tt = 0; tt < 4; tt++) {
            int tile = gt * 4 + tt;
            uint4 fb = sB[tile * 32 + lane];
            int c0 = 0, c1 = 0, c2 = 0, c3 = 0;
            imma16832(c0, c1, c2, c3, A0[0], A0[1], A0[2], A0[3], fb.x, fb.y);
            imma16832(c0, c1, c2, c3, A1[0], A1[1], A1[2], A1[3], fb.z, fb.w);
            int n0 = tile * 8 + 2 * q;
            float B0 = sBN[n0], B1 = sBN[n0 + 1];
            dL[tt * 2]     = __fmaf_rn(-(float)c0, INVS, B0);
            dL[tt * 2 + 1] = __fmaf_rn(-(float)c1, INVS, B1);
            dH[tt * 2]     = __fmaf_rn(-(float)c2, INVS, B0);
            dH[tt * 2 + 1] = __fmaf_rn(-(float)c3, INVS, B1);
        }
        float mnL = dL[0], mnH = dH[0];
        #pragma unroll
        for (int i = 1; i < 8; i++) { mnL = fminf(mnL, dL[i]); mnH = fminf(mnH, dH[i]); }
        bestL = fminf(bestL, mnL);
        bestH = fminf(bestH, mnH);
        bestL = fminf(bestL, __shfl_xor_sync(0xFFFFFFFFu, bestL, 1));
        bestL = fminf(bestL, __shfl_xor_sync(0xFFFFFFFFu, bestL, 2));
        bestH = fminf(bestH, __shfl_xor_sync(0xFFFFFFFFu, bestH, 1));
        bestH = fminf(bestH, __shfl_xor_sync(0xFFFFFFFFu, bestH, 2));

        float thL = bestL + DELTA, thH = bestH + DELTA;
        #pragma unroll
        for (int tt = 0; tt < 4; tt++) {
            int n0 = (gt * 4 + tt) * 8 + 2 * q;
            if (dL[tt * 2]     < thL) append_cand(p0 + r,     n0,     dL[tt * 2]);
            if (dL[tt * 2 + 1] < thL) append_cand(p0 + r,     n0 + 1, dL[tt * 2 + 1]);
            if (dH[tt * 2]     < thH) append_cand(p0 + r + 8, n0,     dH[tt * 2]);
            if (dH[tt * 2 + 1] < thH) append_cand(p0 + r + 8, n0 + 1, dH[tt * 2 + 1]);
        }
    }

    if (q == 0) {
        g_best[p0 + r]     = bestL;
        g_best[p0 + r + 8] = bestH;
    }
}

// ---------------- kernel 3: fused exact rescore + quantize + STE + losses ----------------
__global__ void __launch_bounds__(256) finish_kernel(const float* __restrict__ x,
                                                     const float* __restrict__ w,
                                                     float* __restrict__ out) {
    __shared__ double sd[256];
    __shared__ float  sf[256];
    __shared__ bool   isLast;

    int tid = threadIdx.x;
    int p   = blockIdx.x * 256 + tid;
    int b   = p >> 10;
    int hw  = p & 1023;
    const float* xp = x + (size_t)b * 65536 + hw;

    float xv[EMB_DIM];
    float A = 0.0f;
    #pragma unroll
    for (int d = 0; d < EMB_DIM; d++) {
        float v = xp[(size_t)d * 1024];
        xv[d] = v;
        A = __fadd_rn(A, __fmul_rn(v, v));
    }

    int   cnt = g_cnt[p];
    float bb  = g_best[p] + DELTA;
    float bd  = 3.4e38f;
    int   bi  = 0;

    if (cnt > CAP) {                                  // overflow: exact full scan
        for (int k = 0; k < NUM_EMB; k++) {
            const float* e = w + k * EMB_DIM;
            float m = 0.0f;
            #pragma unroll
            for (int d = 0; d < EMB_DIM; d++) m = __fmaf_rn(xv[d], e[d], m);
            float dist = __fsub_rn(__fadd_rn(A, g_codeS[k]), 2.0f * m);
            if (dist < bd) { bd = dist; bi = k; }
        }
    } else {
        for (int j = 0; j < cnt; j++) {
            if (g_cd[p * CAP + j] > bb) continue;
            int k = g_cidx[p * CAP + j];
            const float4* e4 = reinterpret_cast<const float4*>(w + k * EMB_DIM);
            float m = 0.0f;
            #pragma unroll
            for (int d4 = 0; d4 < 16; d4++) {
                float4 ev = e4[d4];
                m = __fmaf_rn(xv[4 * d4],     ev.x, m);
                m = __fmaf_rn(xv[4 * d4 + 1], ev.y, m);
                m = __fmaf_rn(xv[4 * d4 + 2], ev.z, m);
                m = __fmaf_rn(xv[4 * d4 + 3], ev.w, m);
            }
            float dist = __fsub_rn(__fadd_rn(A, g_codeS[k]), 2.0f * m);
            if (dist < bd || (dist == bd && k < bi)) { bd = dist; bi = k; }
        }
    }

    out[NELEM + 2 + p] = (float)bi;                   // idx output
    atomicAdd(&g_counts[bi], 1);

    // quantize + straight-through + loss partial (row gather via LDG.128)
    const float4* wr = reinterpret_cast<const float4*>(w + bi * EMB_DIM);
    float* ob = out + (size_t)b * 65536 + hw;
    double acc = 0.0;
    #pragma unroll
    for (int j = 0; j < 16; j++) {
        float4 qv = wr[j];
        float x0 = xv[4 * j], x1 = xv[4 * j + 1], x2 = xv[4 * j + 2], x3 = xv[4 * j + 3];
        float d0 = __fsub_rn(qv.x, x0), d1 = __fsub_rn(qv.y, x1);
        float d2 = __fsub_rn(qv.z, x2), d3 = __fsub_rn(qv.w, x3);
        ob[(size_t)(4 * j)     * 1024] = __fadd_rn(x0, d0);
        ob[(size_t)(4 * j + 1) * 1024] = __fadd_rn(x1, d1);
        ob[(size_t)(4 * j + 2) * 1024] = __fadd_rn(x2, d2);
        ob[(size_t)(4 * j + 3) * 1024] = __fadd_rn(x3, d3);
        acc += (double)d0 * d0 + (double)d1 * d1 + (double)d2 * d2 + (double)d3 * d3;
    }

    sd[tid] = acc;
    __syncthreads();
    #pragma unroll
    for (int s = 128; s > 0; s >>= 1) {
        if (tid < s) sd[tid] += sd[tid + s];
        __syncthreads();
    }
    if (tid == 0) g_part[blockIdx.x] = sd[0];
    __threadfence();
    if (tid == 0) isLast = (atomicAdd(&g_ticket, 1) == NBLK - 1);
    __syncthreads();

    if (isLast) {                                     // deterministic final reduction
        __threadfence();
        sd[tid] = g_part[tid];

        float f = 0.0f;
        #pragma unroll
        for (int i = 0; i < NUM_EMB / 256; i++) {
            float pr = (float)g_counts[tid * (NUM_EMB / 256) + i] * (1.0f / 65536.0f);
            f += pr * logf(pr + 1e-10f);
        }
        sf[tid] = f;
        __syncthreads();
        #pragma unroll
        for (int st = 128; st > 0; st >>= 1) {
            if (tid < st) { sd[tid] += sd[tid + st]; sf[tid] += sf[tid + st]; }
            __syncthreads();
        }
        if (tid == 0) {
            float m = (float)(sd[0] / (double)NELEM);
            out[NELEM]     = __fadd_rn(m, __fmul_rn(0.25f, m));  // q_loss + 0.25*e_loss
            out[NELEM + 1] = expf(-sf[0]);
        }
    }
}

extern "C" void kernel_launch(void* const* d_in, const int* in_sizes, int n_in,
                              void* d_out, int out_size) {
    const float* x;
    const float* w;
    if (in_sizes[0] == NELEM) { x = (const float*)d_in[0]; w = (const float*)d_in[1]; }
    else                      { x = (const float*)d_in[1]; w = (const float*)d_in[0]; }
    float* out = (float*)d_out;

    cudaFuncSetAttribute(argmin_kernel, cudaFuncAttributeMaxDynamicSharedMemorySize, 69632);

    prep_kernel<<<40, 128>>>(w);
    argmin_kernel<<<NPIX / 128, 256, 69632>>>(x);
    finish_kernel<<<NPIX / 256, 256>>>(x, w, out);
}

// round 6
// speedup vs baseline: 5.3975x; 5.3975x over previous
#include <cuda_runtime.h>
#include <cuda_bf16.h>
#include <cstdint>

#define NUM_EMB 1024
#define EMB_DIM 64
#define NPIX    65536      // 64 * 32 * 32 pixels
#define NELEM   4194304    // 64 * 64 * 32 * 32
#define NBLK    256        // finish-kernel blocks (256 px each)
#define CAP     32         // candidate buffer per pixel
#define DELTA   2e-3f      // screen window >= 2*max_bf16_err + grid slop

// ---------------- device scratch (no allocs allowed) ----------------
__device__ float    g_codeS[NUM_EMB];
__device__ int      g_counts[NUM_EMB];
__device__ double   g_part[NBLK];
__device__ int      g_ticket;
__device__ uint4    g_bfrag[128 * 64];            // [tile][2 groups x 32 lanes] bf16-hi fragments
__device__ int      g_cnt[NPIX];
__device__ unsigned short g_cidx[NPIX * CAP];

// ---------------- helpers ----------------
static __device__ __forceinline__ uint32_t packbf(float a, float b) {
    uint16_t ha = __bfloat16_as_ushort(__float2bfloat16_rn(a));
    uint16_t hb = __bfloat16_as_ushort(__float2bfloat16_rn(b));
    return (uint32_t)ha | ((uint32_t)hb << 16);
}
static __device__ __forceinline__ void mma16816(float& c0, float& c1, float& c2, float& c3,
                                                uint32_t a0, uint32_t a1, uint32_t a2, uint32_t a3,
                                                uint32_t b0, uint32_t b1) {
    asm volatile("mma.sync.aligned.m16n8k16.row.col.f32.bf16.bf16.f32 "
                 "{%0,%1,%2,%3}, {%4,%5,%6,%7}, {%8,%9}, {%0,%1,%2,%3};"
                 : "+f"(c0), "+f"(c1), "+f"(c2), "+f"(c3)
                 : "r"(a0), "r"(a1), "r"(a2), "r"(a3), "r"(b0), "r"(b1));
}
static __device__ __forceinline__ void append_cand(int pix, int idx) {
    int slot = atomicAdd(&g_cnt[pix], 1);
    if (slot < CAP) g_cidx[pix * CAP + slot] = (unsigned short)idx;
}
static __device__ __forceinline__ uint32_t smem_u32(const void* p) {
    uint32_t a;
    asm("{ .reg .u64 t; cvta.to.shared.u64 t, %1; cvt.u32.u64 %0, t; }" : "=r"(a) : "l"(p));
    return a;
}
static __device__ __forceinline__ void cp16(uint32_t dst, const void* gsrc) {
    asm volatile("cp.async.cg.shared.global [%0], [%1], 16;"
                 :: "r"(dst), "l"(__cvta_generic_to_global(gsrc)) : "memory");
}
#define CP_COMMIT() asm volatile("cp.async.commit_group;" ::: "memory")
#define CP_WAIT0()  asm volatile("cp.async.wait_group 0;" ::: "memory")

// ---------------- kernel 1: staged prep — norms + bf16-hi fragments ----------------
// 16 blocks x 256 thr; block handles 64 codes (= 8 MMA tiles)
__global__ void __launch_bounds__(256) prep_kernel(const float* __restrict__ w) {
    __shared__ float se[64 * EMB_DIM];               // 16 KB: this block's codebook rows
    int tid = threadIdx.x;
    int k0  = blockIdx.x * 64;

    // coalesced stage of 64 rows
    const float4* src = reinterpret_cast<const float4*>(w + k0 * EMB_DIM);
    float4*       dst = reinterpret_cast<float4*>(se);
    #pragma unroll
    for (int i = 0; i < 4; i++) dst[tid + 256 * i] = src[tid + 256 * i];
    __syncthreads();

    if (tid < 64) {                                  // exact code norms (validated order)
        const float* row = se + tid * EMB_DIM;
        float s = 0.0f;
        #pragma unroll
        for (int d = 0; d < EMB_DIM; d++)
            s = __fadd_rn(s, __fmul_rn(row[d], row[d]));
        g_codeS[k0 + tid]  = s;
        g_counts[k0 + tid] = 0;
    }
    if (blockIdx.x == 0 && tid == 0) g_ticket = 0;

    // fragments: 8 local tiles x 32 lanes (exact R4 layout)
    int tl   = tid >> 5;                             // local tile 0..7
    int lane = tid & 31;
    int tile = blockIdx.x * 8 + tl;
    int q    = lane & 3;
    const float* e = se + (tl * 8 + (lane >> 2)) * EMB_DIM;

    uint32_t hiw[8];
    #pragma unroll
    for (int s = 0; s < 4; s++) {
        int ks = 16 * s + 2 * q;
        hiw[2 * s]     = packbf(e[ks],     e[ks + 1]);
        hiw[2 * s + 1] = packbf(e[ks + 8], e[ks + 9]);
    }
    g_bfrag[tile * 64 +      lane] = make_uint4(hiw[0], hiw[1], hiw[2], hiw[3]);
    g_bfrag[tile * 64 + 32 + lane] = make_uint4(hiw[4], hiw[5], hiw[6], hiw[7]);
}

// ---------------- kernel 2: HMMA bf16 screen, cp.async-staged B ----------------
__global__ void __launch_bounds__(256) argmin_kernel(const float* __restrict__ x) {
    __shared__ float sBN[NUM_EMB];                   // 4 KB
    __shared__ uint4 sB[2][1024];                    // 2 x 16 KB: 16 tiles per stage

    int tid  = threadIdx.x;
    int warp = tid >> 5;
    int lane = tid & 31;
    int q    = lane & 3;
    int r    = lane >> 2;

    // prefetch stage 0 via cp.async
    uint32_t sb0 = smem_u32(&sB[0][0]);
    uint32_t sb1 = smem_u32(&sB[1][0]);
    #pragma unroll
    for (int i = 0; i < 4; i++) cp16(sb0 + (tid + 256 * i) * 16, &g_bfrag[tid + 256 * i]);
    CP_COMMIT();

    #pragma unroll
    for (int i = 0; i < 4; i++) sBN[tid + 256 * i] = g_codeS[tid + 256 * i];

    int p0b = blockIdx.x * 128;
    if (tid < 128) g_cnt[p0b + tid] = 0;

    // ---- A fragments (bf16 hi of 2x) for this warp's 16 pixels (R4 layout) ----
    int p0 = p0b + warp * 16;
    const float* xb = x + (size_t)(p0 >> 10) * 65536 + (p0 & 1023);  // NCHW, dim stride 1024

    uint32_t Ahi[16];
    #pragma unroll
    for (int s = 0; s < 4; s++) {
        int k0 = 16 * s + 2 * q;
        float p00 = 2.0f * xb[(size_t)k0 * 1024 + r];
        float p01 = 2.0f * xb[(size_t)(k0 + 1) * 1024 + r];
        float p10 = 2.0f * xb[(size_t)k0 * 1024 + r + 8];
        float p11 = 2.0f * xb[(size_t)(k0 + 1) * 1024 + r + 8];
        float p20 = 2.0f * xb[(size_t)(k0 + 8) * 1024 + r];
        float p21 = 2.0f * xb[(size_t)(k0 + 9) * 1024 + r];
        float p30 = 2.0f * xb[(size_t)(k0 + 8) * 1024 + r + 8];
        float p31 = 2.0f * xb[(size_t)(k0 + 9) * 1024 + r + 8];
        Ahi[s * 4 + 0] = packbf(p00, p01);
        Ahi[s * 4 + 1] = packbf(p10, p11);
        Ahi[s * 4 + 2] = packbf(p20, p21);
        Ahi[s * 4 + 3] = packbf(p30, p31);
    }

    float bestL = 3.4e38f, bestH = 3.4e38f;

    for (int s = 0; s < 8; s++) {
        CP_WAIT0();
        __syncthreads();                              // stage s visible; buf (s&1)^1 free
        if (s < 7) {                                  // overlap: load s+1 during compute s
            uint32_t db = ((s + 1) & 1) ? sb1 : sb0;
            const uint4* gsrc = g_bfrag + (s + 1) * 1024;
            #pragma unroll
            for (int i = 0; i < 4; i++) cp16(db + (tid + 256 * i) * 16, gsrc + tid + 256 * i);
            CP_COMMIT();
        }
        const uint4* cur = sB[s & 1];

        #pragma unroll
        for (int g = 0; g < 4; g++) {                 // 4 tiles per shfl group
            float dL[8], dH[8];
            #pragma unroll
            for (int tt = 0; tt < 4; tt++) {
                int tile = s * 16 + g * 4 + tt;
                int tloc = (g * 4 + tt) * 64;
                uint4 f0 = cur[tloc + lane];
                uint4 f1 = cur[tloc + 32 + lane];

                float c0 = 0.f, c1 = 0.f, c2 = 0.f, c3 = 0.f;
                mma16816(c0, c1, c2, c3, Ahi[0],  Ahi[1],  Ahi[2],  Ahi[3],  f0.x, f0.y);
                mma16816(c0, c1, c2, c3, Ahi[4],  Ahi[5],  Ahi[6],  Ahi[7],  f0.z, f0.w);
                mma16816(c0, c1, c2, c3, Ahi[8],  Ahi[9],  Ahi[10], Ahi[11], f1.x, f1.y);
                mma16816(c0, c1, c2, c3, Ahi[12], Ahi[13], Ahi[14], Ahi[15], f1.z, f1.w);

                int n0 = tile * 8 + 2 * q;            // dist~ = ||e||^2 - m (A const/pixel)
                float B0 = sBN[n0], B1 = sBN[n0 + 1];
                dL[tt * 2]     = __fsub_rn(B0, c0);
                dL[tt * 2 + 1] = __fsub_rn(B1, c1);
                dH[tt * 2]     = __fsub_rn(B0, c2);
                dH[tt * 2 + 1] = __fsub_rn(B1, c3);
            }
            float mnL = dL[0], mnH = dH[0];
            #pragma unroll
            for (int i = 1; i < 8; i++) { mnL = fminf(mnL, dL[i]); mnH = fminf(mnH, dH[i]); }
            bestL = fminf(bestL, mnL);
            bestH = fminf(bestH, mnH);
            bestL = fminf(bestL, __shfl_xor_sync(0xFFFFFFFFu, bestL, 1));
            bestL = fminf(bestL, __shfl_xor_sync(0xFFFFFFFFu, bestL, 2));
            bestH = fminf(bestH, __shfl_xor_sync(0xFFFFFFFFu, bestH, 1));
            bestH = fminf(bestH, __shfl_xor_sync(0xFFFFFFFFu, bestH, 2));

            float thL = bestL + DELTA, thH = bestH + DELTA;
            #pragma unroll
            for (int tt = 0; tt < 4; tt++) {
                int n0 = (s * 16 + g * 4 + tt) * 8 + 2 * q;
                if (dL[tt * 2]     < thL) append_cand(p0 + r,     n0);
                if (dL[tt * 2 + 1] < thL) append_cand(p0 + r,     n0 + 1);
                if (dH[tt * 2]     < thH) append_cand(p0 + r + 8, n0);
                if (dH[tt * 2 + 1] < thH) append_cand(p0 + r + 8, n0 + 1);
            }
        }
        __syncthreads();                              // compute s done before buf reuse
    }
}

// ---------------- kernel 3: fused exact rescore + quantize + STE + losses ----------------
__global__ void __launch_bounds__(256) finish_kernel(const float* __restrict__ x,
                                                     const float* __restrict__ w,
                                                     float* __restrict__ out) {
    __shared__ double sd[256];
    __shared__ float  sf[256];
    __shared__ bool   isLast;

    int tid = threadIdx.x;
    int p   = blockIdx.x * 256 + tid;
    int b   = p >> 10;
    int hw  = p & 1023;
    const float* xp = x + (size_t)b * 65536 + hw;

    float xv[EMB_DIM];
    float A = 0.0f;
    #pragma unroll
    for (int d = 0; d < EMB_DIM; d++) {
        float v = xp[(size_t)d * 1024];
        xv[d] = v;
        A = __fadd_rn(A, __fmul_rn(v, v));
    }

    int   cnt = g_cnt[p];
    float bd  = 3.4e38f;
    int   bi  = 0;

    if (cnt > CAP) {                                  // overflow: exact full scan
        for (int k = 0; k < NUM_EMB; k++) {
            const float* e = w + k * EMB_DIM;
            float m = 0.0f;
            #pragma unroll
            for (int d = 0; d < EMB_DIM; d++) m = __fmaf_rn(xv[d], e[d], m);
            float dist = __fsub_rn(__fadd_rn(A, g_codeS[k]), 2.0f * m);
            if (dist < bd) { bd = dist; bi = k; }
        }
    } else {
        for (int j = 0; j < cnt; j++) {
            int k = g_cidx[p * CAP + j];
            const float4* e4 = reinterpret_cast<const float4*>(w + k * EMB_DIM);
            float m = 0.0f;
            #pragma unroll
            for (int d4 = 0; d4 < 16; d4++) {
                float4 ev = e4[d4];
                m = __fmaf_rn(xv[4 * d4],     ev.x, m);
                m = __fmaf_rn(xv[4 * d4 + 1], ev.y, m);
                m = __fmaf_rn(xv[4 * d4 + 2], ev.z, m);
                m = __fmaf_rn(xv[4 * d4 + 3], ev.w, m);
            }
            float dist = __fsub_rn(__fadd_rn(A, g_codeS[k]), 2.0f * m);
            if (dist < bd || (dist == bd && k < bi)) { bd = dist; bi = k; }
        }
    }

    out[NELEM + 2 + p] = (float)bi;                   // idx output
    atomicAdd(&g_counts[bi], 1);

    // quantize + straight-through + loss partial (row gather via LDG.128)
    const float4* wr = reinterpret_cast<const float4*>(w + bi * EMB_DIM);
    float* ob = out + (size_t)b * 65536 + hw;
    double acc = 0.0;
    #pragma unroll
    for (int j = 0; j < 16; j++) {
        float4 qv = wr[j];
        float x0 = xv[4 * j], x1 = xv[4 * j + 1], x2 = xv[4 * j + 2], x3 = xv[4 * j + 3];
        float d0 = __fsub_rn(qv.x, x0), d1 = __fsub_rn(qv.y, x1);
        float d2 = __fsub_rn(qv.z, x2), d3 = __fsub_rn(qv.w, x3);
        ob[(size_t)(4 * j)     * 1024] = __fadd_rn(x0, d0);
        ob[(size_t)(4 * j + 1) * 1024] = __fadd_rn(x1, d1);
        ob[(size_t)(4 * j + 2) * 1024] = __fadd_rn(x2, d2);
        ob[(size_t)(4 * j + 3) * 1024] = __fadd_rn(x3, d3);
        acc += (double)d0 * d0 + (double)d1 * d1 + (double)d2 * d2 + (double)d3 * d3;
    }

    sd[tid] = acc;
    __syncthreads();
    #pragma unroll
    for (int s = 128; s > 0; s >>= 1) {
        if (tid < s) sd[tid] += sd[tid + s];
        __syncthreads();
    }
    if (tid == 0) g_part[blockIdx.x] = sd[0];
    __threadfence();
    if (tid == 0) isLast = (atomicAdd(&g_ticket, 1) == NBLK - 1);
    __syncthreads();

    if (isLast) {                                     // deterministic final reduction
        __threadfence();
        sd[tid] = g_part[tid];

        float f = 0.0f;
        #pragma unroll
        for (int i = 0; i < NUM_EMB / 256; i++) {
            float pr = (float)g_counts[tid * (NUM_EMB / 256) + i] * (1.0f / 65536.0f);
            f += pr * logf(pr + 1e-10f);
        }
        sf[tid] = f;
        __syncthreads();
        #pragma unroll
        for (int st = 128; st > 0; st >>= 1) {
            if (tid < st) { sd[tid] += sd[tid + st]; sf[tid] += sf[tid + st]; }
            __syncthreads();
        }
        if (tid == 0) {
            float m = (float)(sd[0] / (double)NELEM);
            out[NELEM]     = __fadd_rn(m, __fmul_rn(0.25f, m));  // q_loss + 0.25*e_loss
            out[NELEM + 1] = expf(-sf[0]);
        }
    }
}

extern "C" void kernel_launch(void* const* d_in, const int* in_sizes, int n_in,
                              void* d_out, int out_size) {
    const float* x;
    const float* w;
    if (in_sizes[0] == NELEM) { x = (const float*)d_in[0]; w = (const float*)d_in[1]; }
    else                      { x = (const float*)d_in[1]; w = (const float*)d_in[0]; }
    float* out = (float*)d_out;

    prep_kernel<<<16, 256>>>(w);
    argmin_kernel<<<NPIX / 128, 256>>>(x);
    finish_kernel<<<NPIX / 256, 256>>>(x, w, out);
}

// round 7
// speedup vs baseline: 7.1319x; 1.3213x over previous
#include <cuda_runtime.h>
#include <cuda_bf16.h>
#include <cstdint>

#define NUM_EMB 1024
#define EMB_DIM 64
#define NPIX    65536      // 64 * 32 * 32 pixels
#define NELEM   4194304    // 64 * 64 * 32 * 32
#define NBLK    512        // fused-kernel blocks (128 px each)
#define CAP     32         // candidate buffer per pixel
#define DELTA   2e-3f      // screen window >= 2*max_bf16_err + grid slop

// ---------------- device scratch (no allocs allowed) ----------------
__device__ float    g_codeS[NUM_EMB];
__device__ int      g_counts[NUM_EMB];
__device__ double   g_part[NBLK];
__device__ int      g_ticket;
__device__ uint4    g_bfrag[128 * 64];            // [tile][2 groups x 32 lanes] bf16-hi fragments

// ---------------- helpers ----------------
static __device__ __forceinline__ uint32_t packbf(float a, float b) {
    uint16_t ha = __bfloat16_as_ushort(__float2bfloat16_rn(a));
    uint16_t hb = __bfloat16_as_ushort(__float2bfloat16_rn(b));
    return (uint32_t)ha | ((uint32_t)hb << 16);
}
static __device__ __forceinline__ void mma16816(float& c0, float& c1, float& c2, float& c3,
                                                uint32_t a0, uint32_t a1, uint32_t a2, uint32_t a3,
                                                uint32_t b0, uint32_t b1) {
    asm volatile("mma.sync.aligned.m16n8k16.row.col.f32.bf16.bf16.f32 "
                 "{%0,%1,%2,%3}, {%4,%5,%6,%7}, {%8,%9}, {%0,%1,%2,%3};"
                 : "+f"(c0), "+f"(c1), "+f"(c2), "+f"(c3)
                 : "r"(a0), "r"(a1), "r"(a2), "r"(a3), "r"(b0), "r"(b1));
}
static __device__ __forceinline__ uint32_t smem_u32(const void* p) {
    uint32_t a;
    asm("{ .reg .u64 t; cvta.to.shared.u64 t, %1; cvt.u32.u64 %0, t; }" : "=r"(a) : "l"(p));
    return a;
}
static __device__ __forceinline__ void cp16(uint32_t dst, const void* gsrc) {
    asm volatile("cp.async.cg.shared.global [%0], [%1], 16;"
                 :: "r"(dst), "l"(__cvta_generic_to_global(gsrc)) : "memory");
}
#define CP_COMMIT() asm volatile("cp.async.commit_group;" ::: "memory")
#define CP_WAIT0()  asm volatile("cp.async.wait_group 0;" ::: "memory")

// ---------------- kernel 1: staged prep — norms + bf16-hi fragments ----------------
__global__ void __launch_bounds__(256) prep_kernel(const float* __restrict__ w) {
    __shared__ float se[64 * EMB_DIM];               // 16 KB: this block's codebook rows
    int tid = threadIdx.x;
    int k0  = blockIdx.x * 64;

    const float4* src = reinterpret_cast<const float4*>(w + k0 * EMB_DIM);
    float4*       dst = reinterpret_cast<float4*>(se);
    #pragma unroll
    for (int i = 0; i < 4; i++) dst[tid + 256 * i] = src[tid + 256 * i];
    __syncthreads();

    if (tid < 64) {                                  // exact code norms (validated order)
        const float* row = se + tid * EMB_DIM;
        float s = 0.0f;
        #pragma unroll
        for (int d = 0; d < EMB_DIM; d++)
            s = __fadd_rn(s, __fmul_rn(row[d], row[d]));
        g_codeS[k0 + tid]  = s;
        g_counts[k0 + tid] = 0;
    }
    if (blockIdx.x == 0 && tid == 0) g_ticket = 0;

    int tl   = tid >> 5;
    int lane = tid & 31;
    int tile = blockIdx.x * 8 + tl;
    int q    = lane & 3;
    const float* e = se + (tl * 8 + (lane >> 2)) * EMB_DIM;

    uint32_t hiw[8];
    #pragma unroll
    for (int s = 0; s < 4; s++) {
        int ks = 16 * s + 2 * q;
        hiw[2 * s]     = packbf(e[ks],     e[ks + 1]);
        hiw[2 * s + 1] = packbf(e[ks + 8], e[ks + 9]);
    }
    g_bfrag[tile * 64 +      lane] = make_uint4(hiw[0], hiw[1], hiw[2], hiw[3]);
    g_bfrag[tile * 64 + 32 + lane] = make_uint4(hiw[4], hiw[5], hiw[6], hiw[7]);
}

// ---------------- kernel 2: fused screen + exact rescore + quantize + losses ----------------
__global__ void __launch_bounds__(256, 2) fused_kernel(const float* __restrict__ x,
                                                       const float* __restrict__ w,
                                                       float* __restrict__ out) {
    __shared__ float sBN[NUM_EMB];                   // 4 KB
    __shared__ uint4 sB[2][1024];                    // 32 KB, aliased by sd/sf in phase B
    __shared__ unsigned short sCand[128 * CAP];      // 8 KB
    __shared__ int   sCnt[128];                      // 0.5 KB
    __shared__ bool  isLast;

    double* sd = reinterpret_cast<double*>(&sB[0][0]);         // 256 * 8B
    float*  sf = reinterpret_cast<float*>(&sB[0][0]) + 512;    // 256 * 4B

    int tid  = threadIdx.x;
    int warp = tid >> 5;
    int lane = tid & 31;
    int q    = lane & 3;
    int r    = lane >> 2;
    int p0b  = blockIdx.x * 128;

    // ---------------- phase A: HMMA bf16 screen (R6-identical math) ----------------
    uint32_t sb0 = smem_u32(&sB[0][0]);
    uint32_t sb1 = smem_u32(&sB[1][0]);
    #pragma unroll
    for (int i = 0; i < 4; i++) cp16(sb0 + (tid + 256 * i) * 16, &g_bfrag[tid + 256 * i]);
    CP_COMMIT();

    #pragma unroll
    for (int i = 0; i < 4; i++) sBN[tid + 256 * i] = g_codeS[tid + 256 * i];
    if (tid < 128) sCnt[tid] = 0;

    int p0 = p0b + warp * 16;
    const float* xb = x + (size_t)(p0 >> 10) * 65536 + (p0 & 1023);  // NCHW, dim stride 1024

    uint32_t Ahi[16];
    #pragma unroll
    for (int s = 0; s < 4; s++) {
        int k0 = 16 * s + 2 * q;
        float p00 = 2.0f * xb[(size_t)k0 * 1024 + r];
        float p01 = 2.0f * xb[(size_t)(k0 + 1) * 1024 + r];
        float p10 = 2.0f * xb[(size_t)k0 * 1024 + r + 8];
        float p11 = 2.0f * xb[(size_t)(k0 + 1) * 1024 + r + 8];
        float p20 = 2.0f * xb[(size_t)(k0 + 8) * 1024 + r];
        float p21 = 2.0f * xb[(size_t)(k0 + 9) * 1024 + r];
        float p30 = 2.0f * xb[(size_t)(k0 + 8) * 1024 + r + 8];
        float p31 = 2.0f * xb[(size_t)(k0 + 9) * 1024 + r + 8];
        Ahi[s * 4 + 0] = packbf(p00, p01);
        Ahi[s * 4 + 1] = packbf(p10, p11);
        Ahi[s * 4 + 2] = packbf(p20, p21);
        Ahi[s * 4 + 3] = packbf(p30, p31);
    }

    float bestL = 3.4e38f, bestH = 3.4e38f;
    int lpL = warp * 16 + r;                          // local pixel ids
    int lpH = lpL + 8;

    for (int s = 0; s < 8; s++) {
        CP_WAIT0();
        __syncthreads();
        if (s < 7) {
            uint32_t db = ((s + 1) & 1) ? sb1 : sb0;
            const uint4* gsrc = g_bfrag + (s + 1) * 1024;
            #pragma unroll
            for (int i = 0; i < 4; i++) cp16(db + (tid + 256 * i) * 16, gsrc + tid + 256 * i);
            CP_COMMIT();
        }
        const uint4* cur = sB[s & 1];

        #pragma unroll
        for (int g = 0; g < 4; g++) {
            float dL[8], dH[8];
            #pragma unroll
            for (int tt = 0; tt < 4; tt++) {
                int tile = s * 16 + g * 4 + tt;
                int tloc = (g * 4 + tt) * 64;
                uint4 f0 = cur[tloc + lane];
                uint4 f1 = cur[tloc + 32 + lane];

                float c0 = 0.f, c1 = 0.f, c2 = 0.f, c3 = 0.f;
                mma16816(c0, c1, c2, c3, Ahi[0],  Ahi[1],  Ahi[2],  Ahi[3],  f0.x, f0.y);
                mma16816(c0, c1, c2, c3, Ahi[4],  Ahi[5],  Ahi[6],  Ahi[7],  f0.z, f0.w);
                mma16816(c0, c1, c2, c3, Ahi[8],  Ahi[9],  Ahi[10], Ahi[11], f1.x, f1.y);
                mma16816(c0, c1, c2, c3, Ahi[12], Ahi[13], Ahi[14], Ahi[15], f1.z, f1.w);

                int n0 = tile * 8 + 2 * q;
                float B0 = sBN[n0], B1 = sBN[n0 + 1];
                dL[tt * 2]     = __fsub_rn(B0, c0);
                dL[tt * 2 + 1] = __fsub_rn(B1, c1);
                dH[tt * 2]     = __fsub_rn(B0, c2);
                dH[tt * 2 + 1] = __fsub_rn(B1, c3);
            }
            float mnL = dL[0], mnH = dH[0];
            #pragma unroll
            for (int i = 1; i < 8; i++) { mnL = fminf(mnL, dL[i]); mnH = fminf(mnH, dH[i]); }
            bestL = fminf(bestL, mnL);
            bestH = fminf(bestH, mnH);
            bestL = fminf(bestL, __shfl_xor_sync(0xFFFFFFFFu, bestL, 1));
            bestL = fminf(bestL, __shfl_xor_sync(0xFFFFFFFFu, bestL, 2));
            bestH = fminf(bestH, __shfl_xor_sync(0xFFFFFFFFu, bestH, 1));
            bestH = fminf(bestH, __shfl_xor_sync(0xFFFFFFFFu, bestH, 2));

            float thL = bestL + DELTA, thH = bestH + DELTA;
            #pragma unroll
            for (int tt = 0; tt < 4; tt++) {
                int n0 = (s * 16 + g * 4 + tt) * 8 + 2 * q;
                if (dL[tt * 2] < thL) {
                    int sl = atomicAdd(&sCnt[lpL], 1);
                    if (sl < CAP) sCand[lpL * CAP + sl] = (unsigned short)n0;
                }
                if (dL[tt * 2 + 1] < thL) {
                    int sl = atomicAdd(&sCnt[lpL], 1);
                    if (sl < CAP) sCand[lpL * CAP + sl] = (unsigned short)(n0 + 1);
                }
                if (dH[tt * 2] < thH) {
                    int sl = atomicAdd(&sCnt[lpH], 1);
                    if (sl < CAP) sCand[lpH * CAP + sl] = (unsigned short)n0;
                }
                if (dH[tt * 2 + 1] < thH) {
                    int sl = atomicAdd(&sCnt[lpH], 1);
                    if (sl < CAP) sCand[lpH * CAP + sl] = (unsigned short)(n0 + 1);
                }
            }
        }
        __syncthreads();
    }

    // ---------------- phase B: exact rescore + quantize + STE + loss partials ----------------
    // (sd/sf alias sB -- screen is done with it)
    __syncthreads();

    double acc = 0.0;
    if (tid < 128) {
        int p  = p0b + tid;
        int b  = p >> 10;
        int hw = p & 1023;
        const float* xp = x + (size_t)b * 65536 + hw;

        float xv[EMB_DIM];
        float A = 0.0f;
        #pragma unroll
        for (int d = 0; d < EMB_DIM; d++) {
            float v = xp[(size_t)d * 1024];
            xv[d] = v;
            A = __fadd_rn(A, __fmul_rn(v, v));
        }

        int   cnt = sCnt[tid];
        float bd  = 3.4e38f;
        int   bi  = 0;

        if (cnt > CAP) {                              // overflow: exact full scan
            for (int k = 0; k < NUM_EMB; k++) {
                const float* e = w + k * EMB_DIM;
                float m = 0.0f;
                #pragma unroll
                for (int d = 0; d < EMB_DIM; d++) m = __fmaf_rn(xv[d], e[d], m);
                float dist = __fsub_rn(__fadd_rn(A, g_codeS[k]), 2.0f * m);
                if (dist < bd) { bd = dist; bi = k; }
            }
        } else {
            for (int j = 0; j < cnt; j++) {
                int k = sCand[tid * CAP + j];
                const float4* e4 = reinterpret_cast<const float4*>(w + k * EMB_DIM);
                float m = 0.0f;
                #pragma unroll
                for (int d4 = 0; d4 < 16; d4++) {
                    float4 ev = e4[d4];
                    m = __fmaf_rn(xv[4 * d4],     ev.x, m);
                    m = __fmaf_rn(xv[4 * d4 + 1], ev.y, m);
                    m = __fmaf_rn(xv[4 * d4 + 2], ev.z, m);
                    m = __fmaf_rn(xv[4 * d4 + 3], ev.w, m);
                }
                float dist = __fsub_rn(__fadd_rn(A, g_codeS[k]), 2.0f * m);
                if (dist < bd || (dist == bd && k < bi)) { bd = dist; bi = k; }
            }
        }

        out[NELEM + 2 + p] = (float)bi;               // idx output
        atomicAdd(&g_counts[bi], 1);

        const float4* wr = reinterpret_cast<const float4*>(w + bi * EMB_DIM);
        float* ob = out + (size_t)b * 65536 + hw;
        #pragma unroll
        for (int j = 0; j < 16; j++) {
            float4 qv = wr[j];
            float x0 = xv[4 * j], x1 = xv[4 * j + 1], x2 = xv[4 * j + 2], x3 = xv[4 * j + 3];
            float d0 = __fsub_rn(qv.x, x0), d1 = __fsub_rn(qv.y, x1);
            float d2 = __fsub_rn(qv.z, x2), d3 = __fsub_rn(qv.w, x3);
            ob[(size_t)(4 * j)     * 1024] = __fadd_rn(x0, d0);
            ob[(size_t)(4 * j + 1) * 1024] = __fadd_rn(x1, d1);
            ob[(size_t)(4 * j + 2) * 1024] = __fadd_rn(x2, d2);
            ob[(size_t)(4 * j + 3) * 1024] = __fadd_rn(x3, d3);
            acc += (double)d0 * d0 + (double)d1 * d1 + (double)d2 * d2 + (double)d3 * d3;
        }
    }

    sd[tid] = acc;                                    // upper half contributes 0
    __syncthreads();
    #pragma unroll
    for (int s = 128; s > 0; s >>= 1) {
        if (tid < s) sd[tid] += sd[tid + s];
        __syncthreads();
    }
    if (tid == 0) g_part[blockIdx.x] = sd[0];
    __threadfence();
    if (tid == 0) isLast = (atomicAdd(&g_ticket, 1) == NBLK - 1);
    __syncthreads();

    if (isLast) {                                     // deterministic final reduction
        __threadfence();
        sd[tid] = g_part[tid * 2] + g_part[tid * 2 + 1];

        float f = 0.0f;
        #pragma unroll
        for (int i = 0; i < NUM_EMB / 256; i++) {
            float pr = (float)g_counts[tid * (NUM_EMB / 256) + i] * (1.0f / 65536.0f);
            f += pr * logf(pr + 1e-10f);
        }
        sf[tid] = f;
        __syncthreads();
        #pragma unroll
        for (int st = 128; st > 0; st >>= 1) {
            if (tid < st) { sd[tid] += sd[tid + st]; sf[tid] += sf[tid + st]; }
            __syncthreads();
        }
        if (tid == 0) {
            float m = (float)(sd[0] / (double)NELEM);
            out[NELEM]     = __fadd_rn(m, __fmul_rn(0.25f, m));  // q_loss + 0.25*e_loss
            out[NELEM + 1] = expf(-sf[0]);
        }
    }
}

extern "C" void kernel_launch(void* const* d_in, const int* in_sizes, int n_in,
                              void* d_out, int out_size) {
    const float* x;
    const float* w;
    if (in_sizes[0] == NELEM) { x = (const float*)d_in[0]; w = (const float*)d_in[1]; }
    else                      { x = (const float*)d_in[1]; w = (const float*)d_in[0]; }
    float* out = (float*)d_out;

    prep_kernel<<<16, 256>>>(w);
    fused_kernel<<<NBLK, 256>>>(x, w, out);
}